// round 15
// baseline (speedup 1.0000x reference)
#include <cuda_runtime.h>
#include <cuda_fp16.h>
#include <cstdint>

#define NB 4
#define NS 2048
#define ND 1024
#define NH 16
#define NHD 64

#define NQKV_CTAS 1536   // (24 ncols) x (64 row-blocks)
#define NATT_CTAS 1024   // 64 bh x 16 q-tiles
#define NPRJ_CTAS 512    // (8 ncols) x (64 row-blocks)

// flag segmentation within g_flags
#define ROWF 0     // 64: QKV row-blocks done (target 24)
#define CTXF 64    // 64: ctx row-blocks done (target 16)
#define XF   128   // 64: x fp16 blocks ready (target 1)
#define WQF  192   // 24: Wqkv fp16 col-blocks ready (target 1)
#define WOF  216   // 8:  Wo fp16 blocks ready (target 1)
#define NFLAGS 224

// Scratch (device globals — allocation-free rule)
__device__ __half g_Q[NB*NH*NS*NHD];     // pre-scaled by 0.125*log2(e)
__device__ __half g_K[NB*NH*NS*NHD];
__device__ __half g_V[NB*NH*NS*NHD];     // pad[k] pre-folded
__device__ __half g_ctx[NB*NS*ND];
__device__ __half g_xh[NB*NS*ND];
__device__ __half g_wqkvh[3*ND*ND];
__device__ __half g_woh[ND*ND];
__device__ int    g_flags[NFLAGS];

#define QSCALE 0.1803368801111137f   // 0.125 * log2(e)
#define ONES_H2 0x3C003C00u          // (1.0h, 1.0h)

// ---------------------------------------------------------------------------
// helpers
// ---------------------------------------------------------------------------
__device__ __forceinline__ void mma16(float4& d,
                                      uint32_t a0, uint32_t a1, uint32_t a2, uint32_t a3,
                                      uint32_t b0, uint32_t b1) {
    asm volatile("mma.sync.aligned.m16n8k16.row.col.f32.f16.f16.f32 "
                 "{%0,%1,%2,%3}, {%4,%5,%6,%7}, {%8,%9}, {%0,%1,%2,%3};"
                 : "+f"(d.x), "+f"(d.y), "+f"(d.z), "+f"(d.w)
                 : "r"(a0), "r"(a1), "r"(a2), "r"(a3), "r"(b0), "r"(b1));
}

__device__ __forceinline__ void ldm_x4(uint32_t& r0, uint32_t& r1, uint32_t& r2, uint32_t& r3,
                                       uint32_t addr) {
    asm volatile("ldmatrix.sync.aligned.m8n8.x4.shared.b16 {%0,%1,%2,%3}, [%4];"
                 : "=r"(r0), "=r"(r1), "=r"(r2), "=r"(r3) : "r"(addr));
}

__device__ __forceinline__ void ldm_x4t(uint32_t& r0, uint32_t& r1, uint32_t& r2, uint32_t& r3,
                                        uint32_t addr) {
    asm volatile("ldmatrix.sync.aligned.m8n8.x4.trans.shared.b16 {%0,%1,%2,%3}, [%4];"
                 : "=r"(r0), "=r"(r1), "=r"(r2), "=r"(r3) : "r"(addr));
}

__device__ __forceinline__ void cp16s(uint32_t sa, const void* g) {
    asm volatile("cp.async.cg.shared.global [%0], [%1], 16;" :: "r"(sa), "l"(g) : "memory");
}
__device__ __forceinline__ void cp_commit() { asm volatile("cp.async.commit_group;" ::: "memory"); }
__device__ __forceinline__ void cp_wait1()  { asm volatile("cp.async.wait_group 1;" ::: "memory"); }
__device__ __forceinline__ void cp_wait0()  { asm volatile("cp.async.wait_group 0;" ::: "memory"); }

__device__ __forceinline__ float ex2f(float x) {
    float y;
    asm("ex2.approx.ftz.f32 %0, %1;" : "=f"(y) : "f"(x));
    return y;
}
__device__ __forceinline__ uint32_t packh2(float lo, float hi) {
    uint32_t r;
    asm("cvt.rn.satfinite.f16x2.f32 %0, %1, %2;" : "=r"(r) : "f"(hi), "f"(lo));
    return r;
}
__device__ __forceinline__ uint32_t ex2h2(uint32_t x) {
    uint32_t r;
    asm("ex2.approx.f16x2 %0, %1;" : "=r"(r) : "r"(x));
    return r;
}

// flag primitives (gpu scope)
__device__ __forceinline__ void red_release(int* p) {
    asm volatile("red.release.gpu.global.add.s32 [%0], 1;" :: "l"(p) : "memory");
}
__device__ __forceinline__ int ld_acquire(const int* p) {
    int v;
    asm volatile("ld.acquire.gpu.global.b32 %0, [%1];" : "=r"(v) : "l"(p) : "memory");
    return v;
}
__device__ __forceinline__ void wait_flag(const int* p, int target) {
    if (threadIdx.x == 0) {
        while (ld_acquire(p) < target) __nanosleep(128);
    }
    __syncthreads();
}

// ---------------------------------------------------------------------------
// convert one 128x1024 fp32 block (32768 float4) to fp16 (all 256 threads)
// ---------------------------------------------------------------------------
__device__ void conv_block(const float* __restrict__ src, __half* __restrict__ dst,
                           int blk)
{
    const int base = blk * 32768;
    #pragma unroll 4
    for (int i = threadIdx.x; i < 32768; i += 256) {
        float4 v = ((const float4*)src)[base + i];
        ((__half2*)dst)[(base + i) * 2]     = __floats2half2_rn(v.x, v.y);
        ((__half2*)dst)[(base + i) * 2 + 1] = __floats2half2_rn(v.z, v.w);
    }
}

// ---------------------------------------------------------------------------
// GEMM body (NT) — round-10 proven: BM=BN=128, BK=64 halves, 8 warps (4x2),
// warp tile 32x64, 3-stage cp.async, one barrier per stage.
// EPI==0: QKV scatter (Q pre-scaled, V pad-folded) + row flag release.
// EPI==1: fp32 store + bias.
// ---------------------------------------------------------------------------
template<int EPI, int NDIM>
__device__ void gemm_body(char* smem, int bx, int by,
                          const __half* __restrict__ A, const __half* __restrict__ W,
                          const float* __restrict__ bias, float* __restrict__ C,
                          const int* __restrict__ pad)
{
    const uint32_t sb = (uint32_t)__cvta_generic_to_shared(smem);
    const int tid  = threadIdx.x;
    const int warp = tid >> 5;
    const int lane = tid & 31;
    const int m0 = by * 128;
    const int n0 = bx * 128;
    const int wm = warp >> 1;
    const int wn = warp & 1;
    const int gq = lane >> 2;
    const int t = lane & 3;

    float4 acc[2][8];
    #pragma unroll
    for (int i = 0; i < 2; i++)
        #pragma unroll
        for (int j = 0; j < 8; j++) acc[i][j] = make_float4(0.f,0.f,0.f,0.f);

    auto issue = [&](int buf, int k0) {
        uint32_t base = sb + buf * 32768;
        #pragma unroll
        for (int it = 0; it < 4; it++) {
            int cid = tid + 256 * it;
            int row = cid >> 3;
            int c   = cid & 7;
            int sw  = row * 128 + ((c ^ (row & 7)) << 4);
            cp16s(base + sw,         A + (size_t)(m0 + row) * 1024 + k0 + c * 8);
            cp16s(base + 16384 + sw, W + (size_t)(n0 + row) * 1024 + k0 + c * 8);
        }
    };

    const int NT = 1024 / 64;
    issue(0, 0);  cp_commit();
    issue(1, 64); cp_commit();

    for (int s = 0; s < NT; s++) {
        if (s + 1 < NT) cp_wait1(); else cp_wait0();
        __syncthreads();
        if (s + 2 < NT) { issue((s + 2) % 3, (s + 2) * 64); cp_commit(); }

        const uint32_t As = sb + (s % 3) * 32768;
        const uint32_t Bs = As + 16384;

        #pragma unroll
        for (int ks = 0; ks < 4; ks++) {
            const int ch = ks * 2 + (lane >> 4);
            uint32_t af[2][4];
            #pragma unroll
            for (int i = 0; i < 2; i++) {
                int row = wm * 32 + i * 16 + (lane & 15);
                ldm_x4(af[i][0], af[i][1], af[i][2], af[i][3],
                       As + row * 128 + ((ch ^ (row & 7)) << 4));
            }
            uint32_t bf[8][2];
            #pragma unroll
            for (int jj = 0; jj < 4; jj++) {
                int row = wn * 64 + jj * 16 + (lane & 15);
                uint32_t r0, r1, r2, r3;
                ldm_x4(r0, r1, r2, r3, Bs + row * 128 + ((ch ^ (row & 7)) << 4));
                bf[2*jj][0]   = r0; bf[2*jj][1]   = r2;
                bf[2*jj+1][0] = r1; bf[2*jj+1][1] = r3;
            }
            #pragma unroll
            for (int i = 0; i < 2; i++)
                #pragma unroll
                for (int j = 0; j < 8; j++)
                    mma16(acc[i][j], af[i][0], af[i][1], af[i][2], af[i][3],
                          bf[j][0], bf[j][1]);
        }
    }

    if (EPI == 0) {
        #pragma unroll
        for (int i = 0; i < 2; i++) {
            #pragma unroll
            for (int rh = 0; rh < 2; rh++) {
                int m = m0 + wm * 32 + 16 * i + gq + rh * 8;
                int b_ = m >> 11;
                int s_ = m & (NS - 1);
                float pv = pad[b_ * NS + s_] ? 1.f : 0.f;
                #pragma unroll
                for (int j = 0; j < 8; j++) {
                    int c0 = n0 + wn * 64 + 8 * j + 2 * t;
                    float v0 = (rh ? acc[i][j].z : acc[i][j].x) + bias[c0];
                    float v1 = (rh ? acc[i][j].w : acc[i][j].y) + bias[c0 + 1];
                    int head = c0 / 192;
                    int rr = c0 - head * 192;
                    size_t base = ((size_t)(b_ * NH + head) * NS + s_) * NHD;
                    if (rr < 64)
                        *(__half2*)&g_Q[base + rr] =
                            __floats2half2_rn(v0 * QSCALE, v1 * QSCALE);
                    else if (rr < 128)
                        *(__half2*)&g_K[base + rr - 64] = __floats2half2_rn(v0, v1);
                    else
                        *(__half2*)&g_V[base + rr - 128] = __floats2half2_rn(v0 * pv, v1 * pv);
                }
            }
        }
        __threadfence();
        __syncthreads();
        if (tid == 0) red_release(&g_flags[ROWF + (m0 >> 7)]);
    } else {
        #pragma unroll
        for (int i = 0; i < 2; i++) {
            int r0 = m0 + wm * 32 + 16 * i + gq;
            int r1 = r0 + 8;
            #pragma unroll
            for (int j = 0; j < 8; j++) {
                int c0 = n0 + wn * 64 + 8 * j + 2 * t;
                float b0v = bias[c0], b1v = bias[c0 + 1];
                *(float2*)&C[(size_t)r0 * NDIM + c0] =
                    make_float2(acc[i][j].x + b0v, acc[i][j].y + b1v);
                *(float2*)&C[(size_t)r1 * NDIM + c0] =
                    make_float2(acc[i][j].z + b0v, acc[i][j].w + b1v);
            }
        }
    }
}

// ---------------------------------------------------------------------------
// Flash attention body — round-10 proven: 128-row Q tile, 8 warps, cp.async
// double-buffered 64-row K/V tiles, hoisted Q fragments, f16x2 exp, row-sum
// via ones-mma, dead-tile skip. V pad-folded; denominator unpadded; pad[q]
// at output. smem: Q 16K | K0 8K | K1 8K | V0 8K | V1 8K = 48KB
// ---------------------------------------------------------------------------
__device__ void attn_body(char* smem, int b, int h, int qt,
                          const int* __restrict__ pad, const int* __restrict__ amask)
{
    const uint32_t sb = (uint32_t)__cvta_generic_to_shared(smem);
    const uint32_t Qb = sb;

    const int tid = threadIdx.x;
    const int bh = b * NH + h;
    const int q0 = qt * 128;
    const int causal = amask ? (amask[0] != 0) : 1;

    const int warp = tid >> 5;
    const int lane = tid & 31;
    const int rbase = warp * 16;
    const int gq = lane >> 2;
    const int t = lane & 3;

    // wait for own Q row-block, then start Q load
    wait_flag(&g_flags[ROWF + b * 16 + qt], 24);
    {
        const __half* Qg = g_Q + ((size_t)bh * NS + q0) * NHD;
        #pragma unroll
        for (int it = 0; it < 4; it++) {
            int cid = tid + 256 * it;
            int row = cid >> 3;
            int c   = cid & 7;
            cp16s(Qb + row * 128 + ((c ^ (row & 7)) << 4), Qg + row * 64 + c * 8);
        }
    }
    cp_commit();   // group 0

    // wait for the remaining K/V row-blocks while Q flies
    const int kneed = causal ? qt : 15;
    for (int i = 0; i < kneed; i++)
        wait_flag(&g_flags[ROWF + b * 16 + i], 24);

    const int ktmax = causal ? (2 * qt + 1) : (NS / 64 - 1);

    auto issue_kv = [&](int buf, int k0) {
        const __half* Kg = g_K + ((size_t)bh * NS + k0) * NHD;
        const __half* Vg = g_V + ((size_t)bh * NS + k0) * NHD;
        uint32_t Kb = sb + 16384 + buf * 8192;
        uint32_t Vb = sb + 32768 + buf * 8192;
        #pragma unroll
        for (int it = 0; it < 2; it++) {
            int cid = tid + 256 * it;
            int row = cid >> 3;
            int c   = cid & 7;
            int off = row * 128 + ((c ^ (row & 7)) << 4);
            cp16s(Kb + off, Kg + row * 64 + c * 8);
            cp16s(Vb + off, Vg + row * 64 + c * 8);
        }
    };

    issue_kv(0, 0);   // group 1
    cp_commit();

    cp_wait1();       // Q arrived
    __syncthreads();
    uint32_t qf[4][4];
    #pragma unroll
    for (int ks = 0; ks < 4; ks++) {
        const int ch = ks * 2 + (lane >> 4);
        int row = rbase + (lane & 15);
        ldm_x4(qf[ks][0], qf[ks][1], qf[ks][2], qf[ks][3],
               Qb + row * 128 + ((ch ^ (row & 7)) << 4));
    }

    float m0r = -1e30f, m1r = -1e30f, l0 = 0.f, l1 = 0.f;
    float4 accO[8];
    #pragma unroll
    for (int j = 0; j < 8; j++) accO[j] = make_float4(0.f,0.f,0.f,0.f);

    const int rowa = q0 + rbase + gq;
    const int rowb = rowa + 8;
    const int rowmax = q0 + rbase + 15;

    for (int kt = 0; kt <= ktmax; kt++) {
        const int k0 = kt * 64;

        cp_wait0();
        __syncthreads();

        if (kt + 1 <= ktmax) { issue_kv((kt + 1) & 1, (kt + 1) * 64); cp_commit(); }

        const uint32_t Kb = sb + 16384 + (kt & 1) * 8192;
        const uint32_t Vb = sb + 32768 + (kt & 1) * 8192;

        if (!causal || k0 <= rowmax) {
            float4 sfr[8];
            #pragma unroll
            for (int j = 0; j < 8; j++) sfr[j] = make_float4(0.f,0.f,0.f,0.f);
            #pragma unroll
            for (int ks = 0; ks < 4; ks++) {
                const int ch = ks * 2 + (lane >> 4);
                #pragma unroll
                for (int jj = 0; jj < 4; jj++) {
                    int row = jj * 16 + (lane & 15);
                    uint32_t r0, r1, r2, r3;
                    ldm_x4(r0, r1, r2, r3, Kb + row * 128 + ((ch ^ (row & 7)) << 4));
                    mma16(sfr[2*jj],   qf[ks][0], qf[ks][1], qf[ks][2], qf[ks][3], r0, r2);
                    mma16(sfr[2*jj+1], qf[ks][0], qf[ks][1], qf[ks][2], qf[ks][3], r1, r3);
                }
            }

            const bool diag = causal && (k0 + 63 > q0 + rbase);
            float mx0 = -1e30f, mx1 = -1e30f;
            #pragma unroll
            for (int j = 0; j < 8; j++) {
                if (diag) {
                    int c0 = k0 + 8 * j + 2 * t;
                    int c1 = c0 + 1;
                    if (c0 > rowa) sfr[j].x = -1e30f;
                    if (c1 > rowa) sfr[j].y = -1e30f;
                    if (c0 > rowb) sfr[j].z = -1e30f;
                    if (c1 > rowb) sfr[j].w = -1e30f;
                }
                mx0 = fmaxf(mx0, fmaxf(sfr[j].x, sfr[j].y));
                mx1 = fmaxf(mx1, fmaxf(sfr[j].z, sfr[j].w));
            }
            #pragma unroll
            for (int off = 1; off < 4; off <<= 1) {
                mx0 = fmaxf(mx0, __shfl_xor_sync(0xffffffffu, mx0, off));
                mx1 = fmaxf(mx1, __shfl_xor_sync(0xffffffffu, mx1, off));
            }
            float nm0 = fmaxf(m0r, mx0);
            float nm1 = fmaxf(m1r, mx1);
            float al0 = ex2f(m0r - nm0);
            float al1 = ex2f(m1r - nm1);
            m0r = nm0;  m1r = nm1;

            uint32_t ph[16];
            float4 ls = make_float4(0.f, 0.f, 0.f, 0.f);
            #pragma unroll
            for (int ks = 0; ks < 4; ks++) {
                uint32_t a0 = ex2h2(packh2(sfr[2*ks].x   - nm0, sfr[2*ks].y   - nm0));
                uint32_t a1 = ex2h2(packh2(sfr[2*ks].z   - nm1, sfr[2*ks].w   - nm1));
                uint32_t a2 = ex2h2(packh2(sfr[2*ks+1].x - nm0, sfr[2*ks+1].y - nm0));
                uint32_t a3 = ex2h2(packh2(sfr[2*ks+1].z - nm1, sfr[2*ks+1].w - nm1));
                ph[4*ks+0] = a0; ph[4*ks+1] = a1; ph[4*ks+2] = a2; ph[4*ks+3] = a3;
                mma16(ls, a0, a1, a2, a3, ONES_H2, ONES_H2);
            }
            l0 = l0 * al0 + ls.x;
            l1 = l1 * al1 + ls.z;
            #pragma unroll
            for (int j = 0; j < 8; j++) {
                accO[j].x *= al0; accO[j].y *= al0;
                accO[j].z *= al1; accO[j].w *= al1;
            }

            #pragma unroll
            for (int ks = 0; ks < 4; ks++) {
                #pragma unroll
                for (int jj = 0; jj < 4; jj++) {
                    int kvrow = ks * 16 + (lane & 15);
                    int dch = jj * 2 + (lane >> 4);
                    uint32_t r0, r1, r2, r3;
                    ldm_x4t(r0, r1, r2, r3, Vb + kvrow * 128 + ((dch ^ (kvrow & 7)) << 4));
                    mma16(accO[2*jj],   ph[4*ks+0], ph[4*ks+1], ph[4*ks+2], ph[4*ks+3], r0, r1);
                    mma16(accO[2*jj+1], ph[4*ks+0], ph[4*ks+1], ph[4*ks+2], ph[4*ks+3], r2, r3);
                }
            }
        }
    }

    // finalize: /l, pad[q], store half ctx; release ctx flag
    float pq0 = pad[b * NS + rowa] ? 1.f : 0.f;
    float pq1 = pad[b * NS + rowb] ? 1.f : 0.f;
    float inv0 = pq0 / l0;
    float inv1 = pq1 / l1;
    #pragma unroll
    for (int j = 0; j < 8; j++) {
        int col = h * 64 + 8 * j + 2 * t;
        *(__half2*)&g_ctx[((size_t)b * NS + rowa) * ND + col] =
            __floats2half2_rn(accO[j].x * inv0, accO[j].y * inv0);
        *(__half2*)&g_ctx[((size_t)b * NS + rowb) * ND + col] =
            __floats2half2_rn(accO[j].z * inv1, accO[j].w * inv1);
    }
    __threadfence();
    __syncthreads();
    if (tid == 0) red_release(&g_flags[CTXF + b * 16 + qt]);
}

// ---------------------------------------------------------------------------
// Fused kernel (round-10 phase-major ordering), conversion folded into the
// leading QKV CTAs:
//   QKV CTA (by, bx=0) converts x block by -> xflag[by]
//   QKV CTA (by=0, bx) converts Wqkv block bx -> wqflag[bx]; bx<8 also Wo.
// [0,1536) QKV | [1536,2560) attention | [2560,3072) proj
// ---------------------------------------------------------------------------
__global__ void __launch_bounds__(256, 2)
fused_mha(const float* __restrict__ x, const float* __restrict__ Wqkv,
          const float* __restrict__ Wo,
          const float* __restrict__ bqkv,
          const int* __restrict__ pad, const int* __restrict__ amask,
          const float* __restrict__ bo, float* __restrict__ out)
{
    extern __shared__ char smem[];
    const int bid = blockIdx.x;

    if (bid < NQKV_CTAS) {
        const int bx = bid % 24;
        const int by = bid / 24;

        // inline conversions by the leading CTAs of each group
        bool released = false;
        if (bx == 0) { conv_block(x, g_xh, by); released = true; }
        if (by == 0) {
            conv_block(Wqkv, g_wqkvh, bx);
            if (bx < 8) conv_block(Wo, g_woh, bx);
            released = true;
        }
        if (released) {
            __threadfence();
            __syncthreads();
            if (threadIdx.x == 0) {
                if (bx == 0) red_release(&g_flags[XF + by]);
                if (by == 0) {
                    red_release(&g_flags[WQF + bx]);
                    if (bx < 8) red_release(&g_flags[WOF + bx]);
                }
            }
        }

        wait_flag(&g_flags[XF + by], 1);
        wait_flag(&g_flags[WQF + bx], 1);
        gemm_body<0, 3*ND>(smem, bx, by, g_xh, g_wqkvh, bqkv, nullptr, pad);
    } else if (bid < NQKV_CTAS + NATT_CTAS) {
        int aid = bid - NQKV_CTAS;
        int b   = aid >> 8;            // batch asc (matches QKV completion order)
        int idx = aid & 255;
        int qt  = 15 - (idx >> 4);     // heavy q-tiles first within batch
        int h   = idx & 15;
        attn_body(smem, b, h, qt, pad, amask);
    } else {
        int pid = bid - NQKV_CTAS - NATT_CTAS;
        int mb  = pid >> 3;
        int nb  = pid & 7;
        wait_flag(&g_flags[WOF + nb], 1);
        wait_flag(&g_flags[CTXF + mb], 16);
        gemm_body<1, ND>(smem, nb, mb, g_ctx, g_woh, bo, out, nullptr);
    }
}

// ---------------------------------------------------------------------------
extern "C" void kernel_launch(void* const* d_in, const int* in_sizes, int n_in,
                              void* d_out, int out_size)
{
    const float* x    = (const float*)d_in[0];
    const int*   pad  = (const int*)d_in[1];
    const float* Wqkv = (const float*)d_in[2];
    const float* bqkv = (const float*)d_in[3];
    const float* Wo   = (const float*)d_in[4];
    const float* bo   = (const float*)d_in[5];
    const int*   am   = (n_in > 6) ? (const int*)d_in[6] : nullptr;

    int* flags_ptr = nullptr;
    cudaGetSymbolAddress((void**)&flags_ptr, g_flags);

    const int FUSED_SMEM = 3 * 32768;   // 96 KB (gemm 96KB; attn 48KB)
    cudaFuncSetAttribute(fused_mha, cudaFuncAttributeMaxDynamicSharedMemorySize, FUSED_SMEM);

    // 0) zero dataflow flags (graph-legal async memset)
    cudaMemsetAsync(flags_ptr, 0, NFLAGS * sizeof(int));

    // 1) fully fused convert + QKV + attention + proj (conversion inlined in
    //    leading QKV CTAs — no dedicated converter CTAs, no separate launch)
    fused_mha<<<NQKV_CTAS + NATT_CTAS + NPRJ_CTAS, 256, FUSED_SMEM>>>(
        x, Wqkv, Wo, bqkv, pad, am, bo, (float*)d_out);
}

// round 16
// speedup vs baseline: 1.2857x; 1.2857x over previous
#include <cuda_runtime.h>
#include <cuda_fp16.h>
#include <cstdint>

#define NB 4
#define NS 2048
#define ND 1024
#define NH 16
#define NHD 64

#define NQKV_CTAS 1536   // (24 ncols) x (64 row-blocks)
#define NATT_CTAS 1024   // 64 bh x 16 q-tiles
#define NPRJ_CTAS 512    // (8 ncols) x (64 row-blocks)

// Scratch (device globals — allocation-free rule)
__device__ __half g_Q[NB*NH*NS*NHD];     // pre-scaled by 0.125*log2(e)
__device__ __half g_K[NB*NH*NS*NHD];
__device__ __half g_V[NB*NH*NS*NHD];     // pad[k] pre-folded
__device__ __half g_ctx[NB*NS*ND];
__device__ __half g_xh[NB*NS*ND];
__device__ __half g_wqkvh[3*ND*ND];
__device__ __half g_woh[ND*ND];
__device__ int    g_rowflag[64];         // QKV row-blocks done (target 24)
__device__ int    g_ctxflag[64];         // ctx row-blocks done (target 16)

#define QSCALE 0.1803368801111137f   // 0.125 * log2(e)
#define ONES_H2 0x3C003C00u          // (1.0h, 1.0h)

// ---------------------------------------------------------------------------
// helpers
// ---------------------------------------------------------------------------
__device__ __forceinline__ void mma16(float4& d,
                                      uint32_t a0, uint32_t a1, uint32_t a2, uint32_t a3,
                                      uint32_t b0, uint32_t b1) {
    asm volatile("mma.sync.aligned.m16n8k16.row.col.f32.f16.f16.f32 "
                 "{%0,%1,%2,%3}, {%4,%5,%6,%7}, {%8,%9}, {%0,%1,%2,%3};"
                 : "+f"(d.x), "+f"(d.y), "+f"(d.z), "+f"(d.w)
                 : "r"(a0), "r"(a1), "r"(a2), "r"(a3), "r"(b0), "r"(b1));
}

__device__ __forceinline__ void ldm_x4(uint32_t& r0, uint32_t& r1, uint32_t& r2, uint32_t& r3,
                                       uint32_t addr) {
    asm volatile("ldmatrix.sync.aligned.m8n8.x4.shared.b16 {%0,%1,%2,%3}, [%4];"
                 : "=r"(r0), "=r"(r1), "=r"(r2), "=r"(r3) : "r"(addr));
}

__device__ __forceinline__ void ldm_x4t(uint32_t& r0, uint32_t& r1, uint32_t& r2, uint32_t& r3,
                                        uint32_t addr) {
    asm volatile("ldmatrix.sync.aligned.m8n8.x4.trans.shared.b16 {%0,%1,%2,%3}, [%4];"
                 : "=r"(r0), "=r"(r1), "=r"(r2), "=r"(r3) : "r"(addr));
}

__device__ __forceinline__ void cp16s(uint32_t sa, const void* g) {
    asm volatile("cp.async.cg.shared.global [%0], [%1], 16;" :: "r"(sa), "l"(g) : "memory");
}
__device__ __forceinline__ void cp_commit() { asm volatile("cp.async.commit_group;" ::: "memory"); }
__device__ __forceinline__ void cp_wait1()  { asm volatile("cp.async.wait_group 1;" ::: "memory"); }
__device__ __forceinline__ void cp_wait0()  { asm volatile("cp.async.wait_group 0;" ::: "memory"); }

__device__ __forceinline__ float ex2f(float x) {
    float y;
    asm("ex2.approx.ftz.f32 %0, %1;" : "=f"(y) : "f"(x));
    return y;
}
__device__ __forceinline__ uint32_t packh2(float lo, float hi) {
    uint32_t r;
    asm("cvt.rn.satfinite.f16x2.f32 %0, %1, %2;" : "=r"(r) : "f"(hi), "f"(lo));
    return r;
}
__device__ __forceinline__ uint32_t ex2h2(uint32_t x) {
    uint32_t r;
    asm("ex2.approx.f16x2 %0, %1;" : "=r"(r) : "r"(x));
    return r;
}

// flag primitives (gpu scope)
__device__ __forceinline__ void red_release(int* p) {
    asm volatile("red.release.gpu.global.add.s32 [%0], 1;" :: "l"(p) : "memory");
}
__device__ __forceinline__ int ld_acquire(const int* p) {
    int v;
    asm volatile("ld.acquire.gpu.global.b32 %0, [%1];" : "=r"(v) : "l"(p) : "memory");
    return v;
}
// all threads of CTA wait until *p >= target
__device__ __forceinline__ void wait_flag(const int* p, int target) {
    if (threadIdx.x == 0) {
        while (ld_acquire(p) < target) __nanosleep(128);
    }
    __syncthreads();
}

// ---------------------------------------------------------------------------
// prepass: fp32->fp16 for x/Wqkv/Wo + zero the flags
// ---------------------------------------------------------------------------
__global__ void f2h_all(const float* __restrict__ x,   __half* __restrict__ xh,
                        const float* __restrict__ wq,  __half* __restrict__ wqh,
                        const float* __restrict__ wo,  __half* __restrict__ woh)
{
    if (blockIdx.x == 0 && threadIdx.x < 64) {
        g_rowflag[threadIdx.x] = 0;
        g_ctxflag[threadIdx.x] = 0;
    }
    const int NX4 = NB*NS*ND/4;
    const int NW4 = 3*ND*ND/4;
    const int NO4 = ND*ND/4;
    int i = blockIdx.x * blockDim.x + threadIdx.x;
    if (i < NX4) {
        float4 v = ((const float4*)x)[i];
        ((__half2*)xh)[i*2]   = __floats2half2_rn(v.x, v.y);
        ((__half2*)xh)[i*2+1] = __floats2half2_rn(v.z, v.w);
    }
    if (i < NW4) {
        float4 v = ((const float4*)wq)[i];
        ((__half2*)wqh)[i*2]   = __floats2half2_rn(v.x, v.y);
        ((__half2*)wqh)[i*2+1] = __floats2half2_rn(v.z, v.w);
    }
    if (i < NO4) {
        float4 v = ((const float4*)wo)[i];
        ((__half2*)woh)[i*2]   = __floats2half2_rn(v.x, v.y);
        ((__half2*)woh)[i*2+1] = __floats2half2_rn(v.z, v.w);
    }
}

// ---------------------------------------------------------------------------
// GEMM body (NT): BM=BN=128, BK=64 halves, 8 warps (4x2), warp tile 32x64,
// 3-stage cp.async, one barrier per stage.
// EPI==0: QKV scatter (Q pre-scaled, V pad-folded) + row flag release.
// EPI==1: fp32 store + bias.
// ---------------------------------------------------------------------------
template<int EPI, int NDIM>
__device__ void gemm_body(char* smem, int bx, int by,
                          const __half* __restrict__ A, const __half* __restrict__ W,
                          const float* __restrict__ bias, float* __restrict__ C,
                          const int* __restrict__ pad)
{
    const uint32_t sb = (uint32_t)__cvta_generic_to_shared(smem);
    const int tid  = threadIdx.x;
    const int warp = tid >> 5;
    const int lane = tid & 31;
    const int m0 = by * 128;
    const int n0 = bx * 128;
    const int wm = warp >> 1;
    const int wn = warp & 1;
    const int gq = lane >> 2;
    const int t = lane & 3;

    float4 acc[2][8];
    #pragma unroll
    for (int i = 0; i < 2; i++)
        #pragma unroll
        for (int j = 0; j < 8; j++) acc[i][j] = make_float4(0.f,0.f,0.f,0.f);

    auto issue = [&](int buf, int k0) {
        uint32_t base = sb + buf * 32768;
        #pragma unroll
        for (int it = 0; it < 4; it++) {
            int cid = tid + 256 * it;
            int row = cid >> 3;
            int c   = cid & 7;
            int sw  = row * 128 + ((c ^ (row & 7)) << 4);
            cp16s(base + sw,         A + (size_t)(m0 + row) * 1024 + k0 + c * 8);
            cp16s(base + 16384 + sw, W + (size_t)(n0 + row) * 1024 + k0 + c * 8);
        }
    };

    const int NT = 1024 / 64;
    issue(0, 0);  cp_commit();
    issue(1, 64); cp_commit();

    for (int s = 0; s < NT; s++) {
        if (s + 1 < NT) cp_wait1(); else cp_wait0();
        __syncthreads();
        if (s + 2 < NT) { issue((s + 2) % 3, (s + 2) * 64); cp_commit(); }

        const uint32_t As = sb + (s % 3) * 32768;
        const uint32_t Bs = As + 16384;

        #pragma unroll
        for (int ks = 0; ks < 4; ks++) {
            const int ch = ks * 2 + (lane >> 4);
            uint32_t af[2][4];
            #pragma unroll
            for (int i = 0; i < 2; i++) {
                int row = wm * 32 + i * 16 + (lane & 15);
                ldm_x4(af[i][0], af[i][1], af[i][2], af[i][3],
                       As + row * 128 + ((ch ^ (row & 7)) << 4));
            }
            uint32_t bf[8][2];
            #pragma unroll
            for (int jj = 0; jj < 4; jj++) {
                int row = wn * 64 + jj * 16 + (lane & 15);
                uint32_t r0, r1, r2, r3;
                ldm_x4(r0, r1, r2, r3, Bs + row * 128 + ((ch ^ (row & 7)) << 4));
                bf[2*jj][0]   = r0; bf[2*jj][1]   = r2;
                bf[2*jj+1][0] = r1; bf[2*jj+1][1] = r3;
            }
            #pragma unroll
            for (int i = 0; i < 2; i++)
                #pragma unroll
                for (int j = 0; j < 8; j++)
                    mma16(acc[i][j], af[i][0], af[i][1], af[i][2], af[i][3],
                          bf[j][0], bf[j][1]);
        }
    }

    if (EPI == 0) {
        #pragma unroll
        for (int i = 0; i < 2; i++) {
            #pragma unroll
            for (int rh = 0; rh < 2; rh++) {
                int m = m0 + wm * 32 + 16 * i + gq + rh * 8;
                int b_ = m >> 11;
                int s_ = m & (NS - 1);
                float pv = pad[b_ * NS + s_] ? 1.f : 0.f;
                #pragma unroll
                for (int j = 0; j < 8; j++) {
                    int c0 = n0 + wn * 64 + 8 * j + 2 * t;
                    float v0 = (rh ? acc[i][j].z : acc[i][j].x) + bias[c0];
                    float v1 = (rh ? acc[i][j].w : acc[i][j].y) + bias[c0 + 1];
                    int head = c0 / 192;
                    int rr = c0 - head * 192;
                    size_t base = ((size_t)(b_ * NH + head) * NS + s_) * NHD;
                    if (rr < 64)
                        *(__half2*)&g_Q[base + rr] =
                            __floats2half2_rn(v0 * QSCALE, v1 * QSCALE);
                    else if (rr < 128)
                        *(__half2*)&g_K[base + rr - 64] = __floats2half2_rn(v0, v1);
                    else
                        *(__half2*)&g_V[base + rr - 128] = __floats2half2_rn(v0 * pv, v1 * pv);
                }
            }
        }
        __threadfence();
        __syncthreads();
        if (tid == 0) red_release(&g_rowflag[m0 >> 7]);
    } else {
        #pragma unroll
        for (int i = 0; i < 2; i++) {
            int r0 = m0 + wm * 32 + 16 * i + gq;
            int r1 = r0 + 8;
            #pragma unroll
            for (int j = 0; j < 8; j++) {
                int c0 = n0 + wn * 64 + 8 * j + 2 * t;
                float b0v = bias[c0], b1v = bias[c0 + 1];
                *(float2*)&C[(size_t)r0 * NDIM + c0] =
                    make_float2(acc[i][j].x + b0v, acc[i][j].y + b1v);
                *(float2*)&C[(size_t)r1 * NDIM + c0] =
                    make_float2(acc[i][j].z + b0v, acc[i][j].w + b1v);
            }
        }
    }
}

// ---------------------------------------------------------------------------
// Flash attention body: 128-row Q tile, 8 warps, cp.async double-buffered
// 64-row K/V tiles, hoisted Q fragments, f16x2 exp, row-sum via ones-mma,
// dead-tile skip. V pad-folded; denominator unpadded; pad[q] at output.
// smem: Q 16K | K0 8K | K1 8K | V0 8K | V1 8K = 48KB
// ---------------------------------------------------------------------------
__device__ void attn_body(char* smem, int b, int h, int qt,
                          const int* __restrict__ pad, const int* __restrict__ amask)
{
    const uint32_t sb = (uint32_t)__cvta_generic_to_shared(smem);
    const uint32_t Qb = sb;

    const int tid = threadIdx.x;
    const int bh = b * NH + h;
    const int q0 = qt * 128;
    const int causal = amask ? (amask[0] != 0) : 1;

    const int warp = tid >> 5;
    const int lane = tid & 31;
    const int rbase = warp * 16;
    const int gq = lane >> 2;
    const int t = lane & 3;

    // wait for own Q row-block, then start Q load
    wait_flag(&g_rowflag[b * 16 + qt], 24);
    {
        const __half* Qg = g_Q + ((size_t)bh * NS + q0) * NHD;
        #pragma unroll
        for (int it = 0; it < 4; it++) {
            int cid = tid + 256 * it;
            int row = cid >> 3;
            int c   = cid & 7;
            cp16s(Qb + row * 128 + ((c ^ (row & 7)) << 4), Qg + row * 64 + c * 8);
        }
    }
    cp_commit();   // group 0

    // wait for the remaining K/V row-blocks while Q flies
    const int kneed = causal ? qt : 15;
    for (int i = 0; i < kneed; i++)
        wait_flag(&g_rowflag[b * 16 + i], 24);

    const int ktmax = causal ? (2 * qt + 1) : (NS / 64 - 1);

    auto issue_kv = [&](int buf, int k0) {
        const __half* Kg = g_K + ((size_t)bh * NS + k0) * NHD;
        const __half* Vg = g_V + ((size_t)bh * NS + k0) * NHD;
        uint32_t Kb = sb + 16384 + buf * 8192;
        uint32_t Vb = sb + 32768 + buf * 8192;
        #pragma unroll
        for (int it = 0; it < 2; it++) {
            int cid = tid + 256 * it;
            int row = cid >> 3;
            int c   = cid & 7;
            int off = row * 128 + ((c ^ (row & 7)) << 4);
            cp16s(Kb + off, Kg + row * 64 + c * 8);
            cp16s(Vb + off, Vg + row * 64 + c * 8);
        }
    };

    issue_kv(0, 0);   // group 1
    cp_commit();

    cp_wait1();       // Q arrived
    __syncthreads();
    uint32_t qf[4][4];
    #pragma unroll
    for (int ks = 0; ks < 4; ks++) {
        const int ch = ks * 2 + (lane >> 4);
        int row = rbase + (lane & 15);
        ldm_x4(qf[ks][0], qf[ks][1], qf[ks][2], qf[ks][3],
               Qb + row * 128 + ((ch ^ (row & 7)) << 4));
    }

    float m0r = -1e30f, m1r = -1e30f, l0 = 0.f, l1 = 0.f;
    float4 accO[8];
    #pragma unroll
    for (int j = 0; j < 8; j++) accO[j] = make_float4(0.f,0.f,0.f,0.f);

    const int rowa = q0 + rbase + gq;
    const int rowb = rowa + 8;
    const int rowmax = q0 + rbase + 15;

    for (int kt = 0; kt <= ktmax; kt++) {
        const int k0 = kt * 64;

        cp_wait0();
        __syncthreads();

        if (kt + 1 <= ktmax) { issue_kv((kt + 1) & 1, (kt + 1) * 64); cp_commit(); }

        const uint32_t Kb = sb + 16384 + (kt & 1) * 8192;
        const uint32_t Vb = sb + 32768 + (kt & 1) * 8192;

        if (!causal || k0 <= rowmax) {
            float4 sfr[8];
            #pragma unroll
            for (int j = 0; j < 8; j++) sfr[j] = make_float4(0.f,0.f,0.f,0.f);
            #pragma unroll
            for (int ks = 0; ks < 4; ks++) {
                const int ch = ks * 2 + (lane >> 4);
                #pragma unroll
                for (int jj = 0; jj < 4; jj++) {
                    int row = jj * 16 + (lane & 15);
                    uint32_t r0, r1, r2, r3;
                    ldm_x4(r0, r1, r2, r3, Kb + row * 128 + ((ch ^ (row & 7)) << 4));
                    mma16(sfr[2*jj],   qf[ks][0], qf[ks][1], qf[ks][2], qf[ks][3], r0, r2);
                    mma16(sfr[2*jj+1], qf[ks][0], qf[ks][1], qf[ks][2], qf[ks][3], r1, r3);
                }
            }

            const bool diag = causal && (k0 + 63 > q0 + rbase);
            float mx0 = -1e30f, mx1 = -1e30f;
            #pragma unroll
            for (int j = 0; j < 8; j++) {
                if (diag) {
                    int c0 = k0 + 8 * j + 2 * t;
                    int c1 = c0 + 1;
                    if (c0 > rowa) sfr[j].x = -1e30f;
                    if (c1 > rowa) sfr[j].y = -1e30f;
                    if (c0 > rowb) sfr[j].z = -1e30f;
                    if (c1 > rowb) sfr[j].w = -1e30f;
                }
                mx0 = fmaxf(mx0, fmaxf(sfr[j].x, sfr[j].y));
                mx1 = fmaxf(mx1, fmaxf(sfr[j].z, sfr[j].w));
            }
            #pragma unroll
            for (int off = 1; off < 4; off <<= 1) {
                mx0 = fmaxf(mx0, __shfl_xor_sync(0xffffffffu, mx0, off));
                mx1 = fmaxf(mx1, __shfl_xor_sync(0xffffffffu, mx1, off));
            }
            float nm0 = fmaxf(m0r, mx0);
            float nm1 = fmaxf(m1r, mx1);
            float al0 = ex2f(m0r - nm0);
            float al1 = ex2f(m1r - nm1);
            m0r = nm0;  m1r = nm1;

            uint32_t ph[16];
            float4 ls = make_float4(0.f, 0.f, 0.f, 0.f);
            #pragma unroll
            for (int ks = 0; ks < 4; ks++) {
                uint32_t a0 = ex2h2(packh2(sfr[2*ks].x   - nm0, sfr[2*ks].y   - nm0));
                uint32_t a1 = ex2h2(packh2(sfr[2*ks].z   - nm1, sfr[2*ks].w   - nm1));
                uint32_t a2 = ex2h2(packh2(sfr[2*ks+1].x - nm0, sfr[2*ks+1].y - nm0));
                uint32_t a3 = ex2h2(packh2(sfr[2*ks+1].z - nm1, sfr[2*ks+1].w - nm1));
                ph[4*ks+0] = a0; ph[4*ks+1] = a1; ph[4*ks+2] = a2; ph[4*ks+3] = a3;
                mma16(ls, a0, a1, a2, a3, ONES_H2, ONES_H2);
            }
            l0 = l0 * al0 + ls.x;
            l1 = l1 * al1 + ls.z;
            #pragma unroll
            for (int j = 0; j < 8; j++) {
                accO[j].x *= al0; accO[j].y *= al0;
                accO[j].z *= al1; accO[j].w *= al1;
            }

            #pragma unroll
            for (int ks = 0; ks < 4; ks++) {
                #pragma unroll
                for (int jj = 0; jj < 4; jj++) {
                    int kvrow = ks * 16 + (lane & 15);
                    int dch = jj * 2 + (lane >> 4);
                    uint32_t r0, r1, r2, r3;
                    ldm_x4t(r0, r1, r2, r3, Vb + kvrow * 128 + ((dch ^ (kvrow & 7)) << 4));
                    mma16(accO[2*jj],   ph[4*ks+0], ph[4*ks+1], ph[4*ks+2], ph[4*ks+3], r0, r1);
                    mma16(accO[2*jj+1], ph[4*ks+0], ph[4*ks+1], ph[4*ks+2], ph[4*ks+3], r2, r3);
                }
            }
        }
    }

    // finalize: /l, pad[q], store half ctx; release ctx flag
    float pq0 = pad[b * NS + rowa] ? 1.f : 0.f;
    float pq1 = pad[b * NS + rowb] ? 1.f : 0.f;
    float inv0 = pq0 / l0;
    float inv1 = pq1 / l1;
    #pragma unroll
    for (int j = 0; j < 8; j++) {
        int col = h * 64 + 8 * j + 2 * t;
        *(__half2*)&g_ctx[((size_t)b * NS + rowa) * ND + col] =
            __floats2half2_rn(accO[j].x * inv0, accO[j].y * inv0);
        *(__half2*)&g_ctx[((size_t)b * NS + rowb) * ND + col] =
            __floats2half2_rn(accO[j].z * inv1, accO[j].w * inv1);
    }
    __threadfence();
    __syncthreads();
    if (tid == 0) red_release(&g_ctxflag[b * 16 + qt]);
}

// ---------------------------------------------------------------------------
// Fused kernel: [0,1536) QKV gemm | [1536,2560) attention | [2560,3072) proj
// ---------------------------------------------------------------------------
__global__ void __launch_bounds__(256, 2)
fused_mha(const __half* __restrict__ xh, const __half* __restrict__ wqkvh,
          const float* __restrict__ bqkv,
          const int* __restrict__ pad, const int* __restrict__ amask,
          const __half* __restrict__ ctx, const __half* __restrict__ woh,
          const float* __restrict__ bo, float* __restrict__ out)
{
    extern __shared__ char smem[];
    const int bid = blockIdx.x;

    if (bid < NQKV_CTAS) {
        // row-blocks complete in ascending order (x-major linearization)
        gemm_body<0, 3*ND>(smem, bid % 24, bid / 24, xh, wqkvh, bqkv, nullptr, pad);
    } else if (bid < NQKV_CTAS + NATT_CTAS) {
        int aid = bid - NQKV_CTAS;
        int b   = aid >> 8;            // batch asc (matches QKV completion order)
        int idx = aid & 255;
        int qt  = 15 - (idx >> 4);     // heavy q-tiles first within batch
        int h   = idx & 15;
        attn_body(smem, b, h, qt, pad, amask);
    } else {
        int pid = bid - NQKV_CTAS - NATT_CTAS;
        int mb  = pid >> 3;
        int nb  = pid & 7;
        wait_flag(&g_ctxflag[mb], 16);
        gemm_body<1, ND>(smem, nb, mb, ctx, woh, bo, out, nullptr);
    }
}

// ---------------------------------------------------------------------------
extern "C" void kernel_launch(void* const* d_in, const int* in_sizes, int n_in,
                              void* d_out, int out_size)
{
    const float* x    = (const float*)d_in[0];
    const int*   pad  = (const int*)d_in[1];
    const float* Wqkv = (const float*)d_in[2];
    const float* bqkv = (const float*)d_in[3];
    const float* Wo   = (const float*)d_in[4];
    const float* bo   = (const float*)d_in[5];
    const int*   am   = (n_in > 6) ? (const int*)d_in[6] : nullptr;

    __half *xh, *wqkvh, *woh, *ctx;
    cudaGetSymbolAddress((void**)&xh,    g_xh);
    cudaGetSymbolAddress((void**)&wqkvh, g_wqkvh);
    cudaGetSymbolAddress((void**)&woh,   g_woh);
    cudaGetSymbolAddress((void**)&ctx,   g_ctx);

    const int FUSED_SMEM = 3 * 32768;   // 96 KB (gemm stages; attn uses 48KB)
    cudaFuncSetAttribute(fused_mha, cudaFuncAttributeMaxDynamicSharedMemorySize, FUSED_SMEM);

    // 0) prepass: fp16 conversion + flag reset (one launch)
    {
        int n4 = NB*NS*ND/4;
        f2h_all<<<(n4 + 255) / 256, 256>>>(x, xh, Wqkv, wqkvh, Wo, woh);
    }

    // 1) fused QKV + attention + proj with flag-based dataflow overlap
    fused_mha<<<NQKV_CTAS + NATT_CTAS + NPRJ_CTAS, 256, FUSED_SMEM>>>(
        xh, wqkvh, bqkv, pad, am, ctx, woh, bo, (float*)d_out);
}

// round 17
// speedup vs baseline: 1.3202x; 1.0268x over previous
#include <cuda_runtime.h>
#include <cuda_fp16.h>
#include <cstdint>

#define NB 4
#define NS 2048
#define ND 1024
#define NH 16
#define NHD 64

#define NQKV_CTAS 1536   // (24 ncols) x (64 row-blocks)
#define NATT_CTAS 1024   // 64 bh x 16 q-tiles
#define NPRJ_CTAS 512    // (8 ncols) x (64 row-blocks)

// Scratch (device globals — allocation-free rule)
__device__ __half g_Q[NB*NH*NS*NHD];     // pre-scaled by 0.125*log2(e)
__device__ __half g_K[NB*NH*NS*NHD];
__device__ __half g_V[NB*NH*NS*NHD];     // pad[k] pre-folded
__device__ __half g_ctx[NB*NS*ND];
__device__ __half g_xh[NB*NS*ND];
__device__ __half g_wqkvh[3*ND*ND];
__device__ __half g_woh[ND*ND];
__device__ int    g_rowflag[64];         // QKV row-blocks done (target 24)
__device__ int    g_ctxflag[64];         // ctx row-blocks done (target 16)

#define QSCALE 0.1803368801111137f   // 0.125 * log2(e)
#define ONES_H2 0x3C003C00u          // (1.0h, 1.0h)

// ---------------------------------------------------------------------------
// helpers
// ---------------------------------------------------------------------------
__device__ __forceinline__ void mma16(float4& d,
                                      uint32_t a0, uint32_t a1, uint32_t a2, uint32_t a3,
                                      uint32_t b0, uint32_t b1) {
    asm volatile("mma.sync.aligned.m16n8k16.row.col.f32.f16.f16.f32 "
                 "{%0,%1,%2,%3}, {%4,%5,%6,%7}, {%8,%9}, {%0,%1,%2,%3};"
                 : "+f"(d.x), "+f"(d.y), "+f"(d.z), "+f"(d.w)
                 : "r"(a0), "r"(a1), "r"(a2), "r"(a3), "r"(b0), "r"(b1));
}

__device__ __forceinline__ void ldm_x4(uint32_t& r0, uint32_t& r1, uint32_t& r2, uint32_t& r3,
                                       uint32_t addr) {
    asm volatile("ldmatrix.sync.aligned.m8n8.x4.shared.b16 {%0,%1,%2,%3}, [%4];"
                 : "=r"(r0), "=r"(r1), "=r"(r2), "=r"(r3) : "r"(addr));
}

__device__ __forceinline__ void ldm_x4t(uint32_t& r0, uint32_t& r1, uint32_t& r2, uint32_t& r3,
                                        uint32_t addr) {
    asm volatile("ldmatrix.sync.aligned.m8n8.x4.trans.shared.b16 {%0,%1,%2,%3}, [%4];"
                 : "=r"(r0), "=r"(r1), "=r"(r2), "=r"(r3) : "r"(addr));
}

__device__ __forceinline__ void cp16s(uint32_t sa, const void* g) {
    asm volatile("cp.async.cg.shared.global [%0], [%1], 16;" :: "r"(sa), "l"(g) : "memory");
}
__device__ __forceinline__ void cp_commit() { asm volatile("cp.async.commit_group;" ::: "memory"); }
__device__ __forceinline__ void cp_wait1()  { asm volatile("cp.async.wait_group 1;" ::: "memory"); }
__device__ __forceinline__ void cp_wait0()  { asm volatile("cp.async.wait_group 0;" ::: "memory"); }

__device__ __forceinline__ float ex2f(float x) {
    float y;
    asm("ex2.approx.ftz.f32 %0, %1;" : "=f"(y) : "f"(x));
    return y;
}
__device__ __forceinline__ uint32_t packh2(float lo, float hi) {
    uint32_t r;
    asm("cvt.rn.satfinite.f16x2.f32 %0, %1, %2;" : "=r"(r) : "f"(hi), "f"(lo));
    return r;
}
__device__ __forceinline__ uint32_t ex2h2(uint32_t x) {
    uint32_t r;
    asm("ex2.approx.f16x2 %0, %1;" : "=r"(r) : "r"(x));
    return r;
}

// flag primitives (gpu scope)
__device__ __forceinline__ void red_release(int* p) {
    asm volatile("red.release.gpu.global.add.s32 [%0], 1;" :: "l"(p) : "memory");
}
__device__ __forceinline__ int ld_acquire(const int* p) {
    int v;
    asm volatile("ld.acquire.gpu.global.b32 %0, [%1];" : "=r"(v) : "l"(p) : "memory");
    return v;
}
__device__ __forceinline__ void wait_flag(const int* p, int target) {
    if (threadIdx.x == 0) {
        while (ld_acquire(p) < target) __nanosleep(128);
    }
    __syncthreads();
}

// ---------------------------------------------------------------------------
// prepass: fp32->fp16 for x/Wqkv/Wo + zero the flags
// ---------------------------------------------------------------------------
__global__ void f2h_all(const float* __restrict__ x,   __half* __restrict__ xh,
                        const float* __restrict__ wq,  __half* __restrict__ wqh,
                        const float* __restrict__ wo,  __half* __restrict__ woh)
{
    if (blockIdx.x == 0 && threadIdx.x < 64) {
        g_rowflag[threadIdx.x] = 0;
        g_ctxflag[threadIdx.x] = 0;
    }
    const int NX4 = NB*NS*ND/4;
    const int NW4 = 3*ND*ND/4;
    const int NO4 = ND*ND/4;
    int i = blockIdx.x * blockDim.x + threadIdx.x;
    if (i < NX4) {
        float4 v = ((const float4*)x)[i];
        ((__half2*)xh)[i*2]   = __floats2half2_rn(v.x, v.y);
        ((__half2*)xh)[i*2+1] = __floats2half2_rn(v.z, v.w);
    }
    if (i < NW4) {
        float4 v = ((const float4*)wq)[i];
        ((__half2*)wqh)[i*2]   = __floats2half2_rn(v.x, v.y);
        ((__half2*)wqh)[i*2+1] = __floats2half2_rn(v.z, v.w);
    }
    if (i < NO4) {
        float4 v = ((const float4*)wo)[i];
        ((__half2*)woh)[i*2]   = __floats2half2_rn(v.x, v.y);
        ((__half2*)woh)[i*2+1] = __floats2half2_rn(v.z, v.w);
    }
}

// ---------------------------------------------------------------------------
// GEMM body (NT): BM=BN=128, BK=64 halves, 8 warps (4x2), warp tile 32x64,
// 3-stage cp.async, one barrier per stage. Strength-reduced swizzle
// addressing: fragment addr = base ^ (ks*32) + {0,2048,...} (identical bits).
// EPI==0: QKV scatter (Q pre-scaled, V pad-folded) + row flag release.
// EPI==1: fp32 store + bias.
// ---------------------------------------------------------------------------
template<int EPI, int NDIM>
__device__ void gemm_body(char* smem, int bx, int by,
                          const __half* __restrict__ A, const __half* __restrict__ W,
                          const float* __restrict__ bias, float* __restrict__ C,
                          const int* __restrict__ pad)
{
    const uint32_t sb = (uint32_t)__cvta_generic_to_shared(smem);
    const int tid  = threadIdx.x;
    const int warp = tid >> 5;
    const int lane = tid & 31;
    const int m0 = by * 128;
    const int n0 = bx * 128;
    const int wm = warp >> 1;
    const int wn = warp & 1;
    const int gq = lane >> 2;
    const int t = lane & 3;
    const int l15 = lane & 15;
    const int hi  = lane >> 4;

    float4 acc[2][8];
    #pragma unroll
    for (int i = 0; i < 2; i++)
        #pragma unroll
        for (int j = 0; j < 8; j++) acc[i][j] = make_float4(0.f,0.f,0.f,0.f);

    // strength-reduced cp.async issue: row += 32 per it keeps (row&7) fixed
    auto issue = [&](int buf, int k0) {
        uint32_t base = sb + buf * 32768;
        int row0 = tid >> 3;
        int c0   = tid & 7;
        uint32_t sw = row0 * 128 + ((c0 ^ (row0 & 7)) << 4);
        const __half* ag = A + (size_t)(m0 + row0) * 1024 + k0 + c0 * 8;
        const __half* wg = W + (size_t)(n0 + row0) * 1024 + k0 + c0 * 8;
        #pragma unroll
        for (int it = 0; it < 4; it++) {
            cp16s(base + sw,         ag);
            cp16s(base + 16384 + sw, wg);
            sw += 4096;
            ag += 32 * 1024;
            wg += 32 * 1024;
        }
    };

    // fragment base addresses (swizzle XOR folded once)
    const int arow = wm * 32 + l15;
    const int brow = wn * 64 + l15;
    const uint32_t aoff = (uint32_t)(arow * 128 + ((hi ^ (arow & 7)) << 4));
    const uint32_t boff = (uint32_t)(16384 + brow * 128 + ((hi ^ (brow & 7)) << 4));

    const int NT = 1024 / 64;
    issue(0, 0);  cp_commit();
    issue(1, 64); cp_commit();

    for (int s = 0; s < NT; s++) {
        if (s + 1 < NT) cp_wait1(); else cp_wait0();
        __syncthreads();
        if (s + 2 < NT) { issue((s + 2) % 3, (s + 2) * 64); cp_commit(); }

        const uint32_t stg = sb + (s % 3) * 32768;
        const uint32_t abase = stg + aoff;
        const uint32_t bbase = stg + boff;

        #pragma unroll
        for (int ks = 0; ks < 4; ks++) {
            const uint32_t ax = abase ^ (uint32_t)(ks * 32);
            const uint32_t bxa = bbase ^ (uint32_t)(ks * 32);
            uint32_t af[2][4];
            ldm_x4(af[0][0], af[0][1], af[0][2], af[0][3], ax);
            ldm_x4(af[1][0], af[1][1], af[1][2], af[1][3], ax + 2048);
            uint32_t bf[8][2];
            #pragma unroll
            for (int jj = 0; jj < 4; jj++) {
                uint32_t r0, r1, r2, r3;
                ldm_x4(r0, r1, r2, r3, bxa + jj * 2048);
                bf[2*jj][0]   = r0; bf[2*jj][1]   = r2;
                bf[2*jj+1][0] = r1; bf[2*jj+1][1] = r3;
            }
            #pragma unroll
            for (int i = 0; i < 2; i++)
                #pragma unroll
                for (int j = 0; j < 8; j++)
                    mma16(acc[i][j], af[i][0], af[i][1], af[i][2], af[i][3],
                          bf[j][0], bf[j][1]);
        }
    }

    if (EPI == 0) {
        #pragma unroll
        for (int i = 0; i < 2; i++) {
            #pragma unroll
            for (int rh = 0; rh < 2; rh++) {
                int m = m0 + wm * 32 + 16 * i + gq + rh * 8;
                int b_ = m >> 11;
                int s_ = m & (NS - 1);
                float pv = pad[b_ * NS + s_] ? 1.f : 0.f;
                #pragma unroll
                for (int j = 0; j < 8; j++) {
                    int c0 = n0 + wn * 64 + 8 * j + 2 * t;
                    float v0 = (rh ? acc[i][j].z : acc[i][j].x) + bias[c0];
                    float v1 = (rh ? acc[i][j].w : acc[i][j].y) + bias[c0 + 1];
                    int head = c0 / 192;
                    int rr = c0 - head * 192;
                    size_t base = ((size_t)(b_ * NH + head) * NS + s_) * NHD;
                    if (rr < 64)
                        *(__half2*)&g_Q[base + rr] =
                            __floats2half2_rn(v0 * QSCALE, v1 * QSCALE);
                    else if (rr < 128)
                        *(__half2*)&g_K[base + rr - 64] = __floats2half2_rn(v0, v1);
                    else
                        *(__half2*)&g_V[base + rr - 128] = __floats2half2_rn(v0 * pv, v1 * pv);
                }
            }
        }
        __threadfence();
        __syncthreads();
        if (tid == 0) red_release(&g_rowflag[m0 >> 7]);
    } else {
        #pragma unroll
        for (int i = 0; i < 2; i++) {
            int r0 = m0 + wm * 32 + 16 * i + gq;
            int r1 = r0 + 8;
            #pragma unroll
            for (int j = 0; j < 8; j++) {
                int c0 = n0 + wn * 64 + 8 * j + 2 * t;
                float b0v = bias[c0], b1v = bias[c0 + 1];
                *(float2*)&C[(size_t)r0 * NDIM + c0] =
                    make_float2(acc[i][j].x + b0v, acc[i][j].y + b1v);
                *(float2*)&C[(size_t)r1 * NDIM + c0] =
                    make_float2(acc[i][j].z + b0v, acc[i][j].w + b1v);
            }
        }
    }
}

// ---------------------------------------------------------------------------
// Flash attention body: 128-row Q tile, 8 warps, cp.async double-buffered
// 64-row K/V tiles, hoisted Q fragments, f16x2 exp, row-sum via ones-mma,
// dead-tile skip, strength-reduced swizzle addressing.
// V pad-folded; denominator unpadded; pad[q] at output.
// smem: Q 16K | K0 8K | K1 8K | V0 8K | V1 8K = 48KB
// ---------------------------------------------------------------------------
__device__ void attn_body(char* smem, int b, int h, int qt,
                          const int* __restrict__ pad, const int* __restrict__ amask)
{
    const uint32_t sb = (uint32_t)__cvta_generic_to_shared(smem);
    const uint32_t Qb = sb;

    const int tid = threadIdx.x;
    const int bh = b * NH + h;
    const int q0 = qt * 128;
    const int causal = amask ? (amask[0] != 0) : 1;

    const int warp = tid >> 5;
    const int lane = tid & 31;
    const int rbase = warp * 16;
    const int gq = lane >> 2;
    const int t = lane & 3;
    const int l15 = lane & 15;
    const int hi  = lane >> 4;

    // wait for own Q row-block, then start Q load (strength-reduced)
    wait_flag(&g_rowflag[b * 16 + qt], 24);
    {
        const __half* Qg = g_Q + ((size_t)bh * NS + q0) * NHD;
        int row0 = tid >> 3;
        int c0   = tid & 7;
        uint32_t sw = row0 * 128 + ((c0 ^ (row0 & 7)) << 4);
        const __half* qg = Qg + row0 * 64 + c0 * 8;
        #pragma unroll
        for (int it = 0; it < 4; it++) {
            cp16s(Qb + sw, qg);
            sw += 4096;
            qg += 32 * 64;
        }
    }
    cp_commit();   // group 0

    // wait for the remaining K/V row-blocks while Q flies
    const int kneed = causal ? qt : 15;
    for (int i = 0; i < kneed; i++)
        wait_flag(&g_rowflag[b * 16 + i], 24);

    const int ktmax = causal ? (2 * qt + 1) : (NS / 64 - 1);

    auto issue_kv = [&](int buf, int k0) {
        const __half* Kg = g_K + ((size_t)bh * NS + k0) * NHD;
        const __half* Vg = g_V + ((size_t)bh * NS + k0) * NHD;
        uint32_t Kb = sb + 16384 + buf * 8192;
        uint32_t Vb = sb + 32768 + buf * 8192;
        int row0 = tid >> 3;
        int c0   = tid & 7;
        uint32_t sw = row0 * 128 + ((c0 ^ (row0 & 7)) << 4);
        const __half* kg = Kg + row0 * 64 + c0 * 8;
        const __half* vg = Vg + row0 * 64 + c0 * 8;
        #pragma unroll
        for (int it = 0; it < 2; it++) {
            cp16s(Kb + sw, kg);
            cp16s(Vb + sw, vg);
            sw += 4096;
            kg += 32 * 64;
            vg += 32 * 64;
        }
    };

    issue_kv(0, 0);   // group 1
    cp_commit();

    cp_wait1();       // Q arrived
    __syncthreads();
    // hoisted Q fragments: qaddr(ks) = qbase ^ (ks*32)
    uint32_t qf[4][4];
    {
        const int qrow = rbase + l15;
        const uint32_t qbase = Qb + qrow * 128 + ((hi ^ (qrow & 7)) << 4);
        #pragma unroll
        for (int ks = 0; ks < 4; ks++)
            ldm_x4(qf[ks][0], qf[ks][1], qf[ks][2], qf[ks][3],
                   qbase ^ (uint32_t)(ks * 32));
    }

    // per-lane swizzle XOR shared by K and V fragments (row&7 = l15&7)
    const uint32_t kvxor = (uint32_t)((hi ^ (l15 & 7)) << 4);

    float m0r = -1e30f, m1r = -1e30f, l0 = 0.f, l1 = 0.f;
    float4 accO[8];
    #pragma unroll
    for (int j = 0; j < 8; j++) accO[j] = make_float4(0.f,0.f,0.f,0.f);

    const int rowa = q0 + rbase + gq;
    const int rowb = rowa + 8;
    const int rowmax = q0 + rbase + 15;

    for (int kt = 0; kt <= ktmax; kt++) {
        const int k0 = kt * 64;

        cp_wait0();
        __syncthreads();

        if (kt + 1 <= ktmax) { issue_kv((kt + 1) & 1, (kt + 1) * 64); cp_commit(); }

        const uint32_t Kb = sb + 16384 + (kt & 1) * 8192;
        const uint32_t Vb = sb + 32768 + (kt & 1) * 8192;

        if (!causal || k0 <= rowmax) {
            const uint32_t kbase = Kb + l15 * 128 + kvxor;
            const uint32_t vbase = Vb + l15 * 128 + kvxor;

            // S = Q @ K^T
            float4 sfr[8];
            #pragma unroll
            for (int j = 0; j < 8; j++) sfr[j] = make_float4(0.f,0.f,0.f,0.f);
            #pragma unroll
            for (int ks = 0; ks < 4; ks++) {
                const uint32_t ka = kbase ^ (uint32_t)(ks * 32);
                #pragma unroll
                for (int jj = 0; jj < 4; jj++) {
                    uint32_t r0, r1, r2, r3;
                    ldm_x4(r0, r1, r2, r3, ka + jj * 2048);
                    mma16(sfr[2*jj],   qf[ks][0], qf[ks][1], qf[ks][2], qf[ks][3], r0, r2);
                    mma16(sfr[2*jj+1], qf[ks][0], qf[ks][1], qf[ks][2], qf[ks][3], r1, r3);
                }
            }

            const bool diag = causal && (k0 + 63 > q0 + rbase);
            float mx0 = -1e30f, mx1 = -1e30f;
            #pragma unroll
            for (int j = 0; j < 8; j++) {
                if (diag) {
                    int c0 = k0 + 8 * j + 2 * t;
                    int c1 = c0 + 1;
                    if (c0 > rowa) sfr[j].x = -1e30f;
                    if (c1 > rowa) sfr[j].y = -1e30f;
                    if (c0 > rowb) sfr[j].z = -1e30f;
                    if (c1 > rowb) sfr[j].w = -1e30f;
                }
                mx0 = fmaxf(mx0, fmaxf(sfr[j].x, sfr[j].y));
                mx1 = fmaxf(mx1, fmaxf(sfr[j].z, sfr[j].w));
            }
            #pragma unroll
            for (int off = 1; off < 4; off <<= 1) {
                mx0 = fmaxf(mx0, __shfl_xor_sync(0xffffffffu, mx0, off));
                mx1 = fmaxf(mx1, __shfl_xor_sync(0xffffffffu, mx1, off));
            }
            float nm0 = fmaxf(m0r, mx0);
            float nm1 = fmaxf(m1r, mx1);
            float al0 = ex2f(m0r - nm0);
            float al1 = ex2f(m1r - nm1);
            m0r = nm0;  m1r = nm1;

            uint32_t ph[16];
            float4 ls = make_float4(0.f, 0.f, 0.f, 0.f);
            #pragma unroll
            for (int ks = 0; ks < 4; ks++) {
                uint32_t a0 = ex2h2(packh2(sfr[2*ks].x   - nm0, sfr[2*ks].y   - nm0));
                uint32_t a1 = ex2h2(packh2(sfr[2*ks].z   - nm1, sfr[2*ks].w   - nm1));
                uint32_t a2 = ex2h2(packh2(sfr[2*ks+1].x - nm0, sfr[2*ks+1].y - nm0));
                uint32_t a3 = ex2h2(packh2(sfr[2*ks+1].z - nm1, sfr[2*ks+1].w - nm1));
                ph[4*ks+0] = a0; ph[4*ks+1] = a1; ph[4*ks+2] = a2; ph[4*ks+3] = a3;
                mma16(ls, a0, a1, a2, a3, ONES_H2, ONES_H2);
            }
            l0 = l0 * al0 + ls.x;
            l1 = l1 * al1 + ls.z;
            #pragma unroll
            for (int j = 0; j < 8; j++) {
                accO[j].x *= al0; accO[j].y *= al0;
                accO[j].z *= al1; accO[j].w *= al1;
            }

            // accO += P @ V ; V addr = (vbase ^ jj*32) + ks*2048 (immediate)
            const uint32_t v0a = vbase;
            const uint32_t v1a = vbase ^ 32u;
            const uint32_t v2a = vbase ^ 64u;
            const uint32_t v3a = vbase ^ 96u;
            #pragma unroll
            for (int ks = 0; ks < 4; ks++) {
                const uint32_t kso = (uint32_t)(ks * 2048);
                uint32_t r0, r1, r2, r3;
                ldm_x4t(r0, r1, r2, r3, v0a + kso);
                mma16(accO[0], ph[4*ks+0], ph[4*ks+1], ph[4*ks+2], ph[4*ks+3], r0, r1);
                mma16(accO[1], ph[4*ks+0], ph[4*ks+1], ph[4*ks+2], ph[4*ks+3], r2, r3);
                ldm_x4t(r0, r1, r2, r3, v1a + kso);
                mma16(accO[2], ph[4*ks+0], ph[4*ks+1], ph[4*ks+2], ph[4*ks+3], r0, r1);
                mma16(accO[3], ph[4*ks+0], ph[4*ks+1], ph[4*ks+2], ph[4*ks+3], r2, r3);
                ldm_x4t(r0, r1, r2, r3, v2a + kso);
                mma16(accO[4], ph[4*ks+0], ph[4*ks+1], ph[4*ks+2], ph[4*ks+3], r0, r1);
                mma16(accO[5], ph[4*ks+0], ph[4*ks+1], ph[4*ks+2], ph[4*ks+3], r2, r3);
                ldm_x4t(r0, r1, r2, r3, v3a + kso);
                mma16(accO[6], ph[4*ks+0], ph[4*ks+1], ph[4*ks+2], ph[4*ks+3], r0, r1);
                mma16(accO[7], ph[4*ks+0], ph[4*ks+1], ph[4*ks+2], ph[4*ks+3], r2, r3);
            }
        }
    }

    // finalize: /l, pad[q], store half ctx; release ctx flag
    float pq0 = pad[b * NS + rowa] ? 1.f : 0.f;
    float pq1 = pad[b * NS + rowb] ? 1.f : 0.f;
    float inv0 = pq0 / l0;
    float inv1 = pq1 / l1;
    #pragma unroll
    for (int j = 0; j < 8; j++) {
        int col = h * 64 + 8 * j + 2 * t;
        *(__half2*)&g_ctx[((size_t)b * NS + rowa) * ND + col] =
            __floats2half2_rn(accO[j].x * inv0, accO[j].y * inv0);
        *(__half2*)&g_ctx[((size_t)b * NS + rowb) * ND + col] =
            __floats2half2_rn(accO[j].z * inv1, accO[j].w * inv1);
    }
    __threadfence();
    __syncthreads();
    if (tid == 0) red_release(&g_ctxflag[b * 16 + qt]);
}

// ---------------------------------------------------------------------------
// Fused kernel: [0,1536) QKV gemm | [1536,2560) attention | [2560,3072) proj
// ---------------------------------------------------------------------------
__global__ void __launch_bounds__(256, 2)
fused_mha(const __half* __restrict__ xh, const __half* __restrict__ wqkvh,
          const float* __restrict__ bqkv,
          const int* __restrict__ pad, const int* __restrict__ amask,
          const __half* __restrict__ ctx, const __half* __restrict__ woh,
          const float* __restrict__ bo, float* __restrict__ out)
{
    extern __shared__ char smem[];
    const int bid = blockIdx.x;

    if (bid < NQKV_CTAS) {
        gemm_body<0, 3*ND>(smem, bid % 24, bid / 24, xh, wqkvh, bqkv, nullptr, pad);
    } else if (bid < NQKV_CTAS + NATT_CTAS) {
        int aid = bid - NQKV_CTAS;
        int b   = aid >> 8;
        int idx = aid & 255;
        int qt  = 15 - (idx >> 4);     // heavy q-tiles first within batch
        int h   = idx & 15;
        attn_body(smem, b, h, qt, pad, amask);
    } else {
        int pid = bid - NQKV_CTAS - NATT_CTAS;
        int mb  = pid >> 3;
        int nb  = pid & 7;
        wait_flag(&g_ctxflag[mb], 16);
        gemm_body<1, ND>(smem, nb, mb, ctx, woh, bo, out, nullptr);
    }
}

// ---------------------------------------------------------------------------
extern "C" void kernel_launch(void* const* d_in, const int* in_sizes, int n_in,
                              void* d_out, int out_size)
{
    const float* x    = (const float*)d_in[0];
    const int*   pad  = (const int*)d_in[1];
    const float* Wqkv = (const float*)d_in[2];
    const float* bqkv = (const float*)d_in[3];
    const float* Wo   = (const float*)d_in[4];
    const float* bo   = (const float*)d_in[5];
    const int*   am   = (n_in > 6) ? (const int*)d_in[6] : nullptr;

    __half *xh, *wqkvh, *woh, *ctx;
    cudaGetSymbolAddress((void**)&xh,    g_xh);
    cudaGetSymbolAddress((void**)&wqkvh, g_wqkvh);
    cudaGetSymbolAddress((void**)&woh,   g_woh);
    cudaGetSymbolAddress((void**)&ctx,   g_ctx);

    const int FUSED_SMEM = 3 * 32768;   // 96 KB (gemm stages; attn uses 48KB)
    cudaFuncSetAttribute(fused_mha, cudaFuncAttributeMaxDynamicSharedMemorySize, FUSED_SMEM);

    // 0) prepass: fp16 conversion + flag reset (one launch)
    {
        int n4 = NB*NS*ND/4;
        f2h_all<<<(n4 + 255) / 256, 256>>>(x, xh, Wqkv, wqkvh, Wo, woh);
    }

    // 1) fused QKV + attention + proj with flag-based dataflow overlap
    fused_mha<<<NQKV_CTAS + NATT_CTAS + NPRJ_CTAS, 256, FUSED_SMEM>>>(
        xh, wqkvh, bqkv, pad, am, ctx, woh, bo, (float*)d_out);
}